// round 5
// baseline (speedup 1.0000x reference)
#include <cuda_runtime.h>
#include <cstdint>

// NetVladCNN: B=64, D=512, H=W=32 (N=1024), K=64
// x: (B,D,H,W) fp32   w: (K,D)   c: (K,D)   out: (D,K,B) fp32
//
// Stage 1 (SIMT FFMA2, 8x8): features[b,k,n] = sum_d w[k,d]*x[b,d,n]
// Stage 2: softmax over h (sum_n a == 32 exactly)
// Stage 3 (SIMT FFMA2, 8x8): C[k,d] = sum_n a[k,n]*x[d,n]; V = C - 32*c;
//         per-(b,d) L2-normalize over k; write g_v[b][d][k]
// Stage 4: transpose g_v [b][dk] -> out [dk][b]

#define BB 64
#define DD 512
#define NN 1024
#define KK 64
#define EPSN 1e-12f
#define PADX 260   // 16n x 260 floats, 1040B row (16B-aligned), conflict-free scalar STS

__device__ float g_a[(size_t)BB * KK * NN];   // features / softmaxed a [b][k][n]
__device__ float g_v[(size_t)BB * DD * KK];   // normalized V [b][d][k]

// ---------- packed f32x2 helpers ----------
__device__ __forceinline__ unsigned long long pack2(float lo, float hi) {
    unsigned long long r;
    asm("mov.b64 %0, {%1,%2};" : "=l"(r) : "f"(lo), "f"(hi));
    return r;
}
__device__ __forceinline__ void ffma2(unsigned long long& d,
                                      unsigned long long a,
                                      unsigned long long b) {
    asm("fma.rn.f32x2 %0, %1, %2, %0;" : "+l"(d) : "l"(a), "l"(b));
}
__device__ __forceinline__ float2 unpack2(unsigned long long v) {
    float2 f;
    asm("mov.b64 {%0,%1}, %2;" : "=f"(f.x), "=f"(f.y) : "l"(v));
    return f;
}

// ============================================================================
// Kernel 1: features GEMM. CTA tile 64k x 256n per b; 256 thr, 8x8/thread.
// ============================================================================
__global__ __launch_bounds__(256, 2) void k_features(const float* __restrict__ x,
                                                     const float* __restrict__ wt) {
    __shared__ float sW[16][68];    // [dd][k]  (transposed w tile)
    __shared__ float sX[16][256];   // [dd][n]

    const int b  = blockIdx.y;
    const int n0 = blockIdx.x * 256;
    const int t  = threadIdx.x;
    const int tx = t & 31;    // n: 8 each -> 256
    const int ty = t >> 5;    // k: 8 each -> 64

    const float* xb = x + (size_t)b * DD * NN;

    unsigned long long acc[8][4];
#pragma unroll
    for (int i = 0; i < 8; i++)
#pragma unroll
        for (int j = 0; j < 4; j++) acc[i][j] = 0ull;

    const int lk = t >> 2;          // w loader: k row 0..63
    const int lj = (t & 3) * 4;     // d offset 0,4,8,12
    const int xr = t >> 6;          // x loader: row 0..3 (+4*r)
    const int xc = (t & 63) * 4;    // col (coalesced, conflict-free STS)

    for (int d0 = 0; d0 < DD; d0 += 16) {
        {
            float4 v = *(const float4*)(wt + lk * DD + d0 + lj);
            sW[lj + 0][lk] = v.x; sW[lj + 1][lk] = v.y;
            sW[lj + 2][lk] = v.z; sW[lj + 3][lk] = v.w;
        }
#pragma unroll
        for (int r = 0; r < 4; r++) {
            float4 v = *(const float4*)(xb + (size_t)(d0 + xr + 4 * r) * NN + n0 + xc);
            *(float4*)&sX[xr + 4 * r][xc] = v;
        }
        __syncthreads();
#pragma unroll
        for (int dd = 0; dd < 16; dd++) {
            float4 ka = *(const float4*)&sW[dd][ty * 8];
            float4 kb = *(const float4*)&sW[dd][ty * 8 + 4];
            float4 x0 = *(const float4*)&sX[dd][tx * 8];
            float4 x1 = *(const float4*)&sX[dd][tx * 8 + 4];
            unsigned long long xp0 = pack2(x0.x, x0.y);
            unsigned long long xp1 = pack2(x0.z, x0.w);
            unsigned long long xp2 = pack2(x1.x, x1.y);
            unsigned long long xp3 = pack2(x1.z, x1.w);
            float kf[8] = {ka.x, ka.y, ka.z, ka.w, kb.x, kb.y, kb.z, kb.w};
#pragma unroll
            for (int i = 0; i < 8; i++) {
                unsigned long long kp = pack2(kf[i], kf[i]);
                ffma2(acc[i][0], kp, xp0);
                ffma2(acc[i][1], kp, xp1);
                ffma2(acc[i][2], kp, xp2);
                ffma2(acc[i][3], kp, xp3);
            }
        }
        __syncthreads();
    }

#pragma unroll
    for (int i = 0; i < 8; i++) {
        float2 a0 = unpack2(acc[i][0]);
        float2 a1 = unpack2(acc[i][1]);
        float2 a2 = unpack2(acc[i][2]);
        float2 a3 = unpack2(acc[i][3]);
        float* dst = &g_a[((size_t)b * KK + ty * 8 + i) * NN + n0 + tx * 8];
        *(float4*)dst       = make_float4(a0.x, a0.y, a1.x, a1.y);
        *(float4*)(dst + 4) = make_float4(a2.x, a2.y, a3.x, a3.y);
    }
}

// ============================================================================
// Kernel 2: softmax over h, per (b,k) row of 1024 = 32h x 32w.
// ============================================================================
__global__ __launch_bounds__(256) void k_softmax() {
    __shared__ float red[8][33];
    const size_t base = (size_t)blockIdx.x * NN;
    const int t = threadIdx.x;
    const int q = t >> 5, w = t & 31;

    float v[4];
#pragma unroll
    for (int u = 0; u < 4; u++) v[u] = g_a[base + t + 256 * u];

    float m = fmaxf(fmaxf(v[0], v[1]), fmaxf(v[2], v[3]));
    red[q][w] = m;
    __syncthreads();
    float mm = red[0][w];
#pragma unroll
    for (int qq = 1; qq < 8; qq++) mm = fmaxf(mm, red[qq][w]);
    __syncthreads();

    float s = 0.f;
#pragma unroll
    for (int u = 0; u < 4; u++) { v[u] = __expf(v[u] - mm); s += v[u]; }
    red[q][w] = s;
    __syncthreads();
    float ss = red[0][w];
#pragma unroll
    for (int qq = 1; qq < 8; qq++) ss += red[qq][w];

    float inv = 1.0f / ss;
#pragma unroll
    for (int u = 0; u < 4; u++) g_a[base + t + 256 * u] = v[u] * inv;
}

// ============================================================================
// Kernel 3: V GEMM. CTA tile 64k x 256d per b; 256 thr, 8x8/thread.
// C[k,d] = sum_n a[k,n]*x[d,n]; epilogue V=C-32c, normalize over k, g_v[b][d][k].
// ============================================================================
__global__ __launch_bounds__(256) void k_vlad(const float* __restrict__ x,
                                              const float* __restrict__ c) {
    __shared__ float sAT[16][68];     // [nn][k]
    __shared__ float sXT[16][PADX];   // [nn][d]
    __shared__ float red[8][256];
    __shared__ float sinv[256];

    const int b  = blockIdx.y;
    const int d0 = blockIdx.x * 256;
    const int t  = threadIdx.x;
    const int tx = t & 31;    // d: 8 each -> 256
    const int ty = t >> 5;    // k: 8 each -> 64

    const float* xb = x + (size_t)b * DD * NN;
    const float* ab = g_a + (size_t)b * KK * NN;

    unsigned long long acc[8][4];
#pragma unroll
    for (int i = 0; i < 8; i++)
#pragma unroll
        for (int j = 0; j < 4; j++) acc[i][j] = 0ull;

    const int ak = t >> 2;          // a loader: k row 0..63
    const int aj = (t & 3) * 4;     // n offset 0,4,8,12

    for (int n0 = 0; n0 < NN; n0 += 16) {
        {
            float4 v = *(const float4*)(ab + (size_t)ak * NN + n0 + aj);
            sAT[aj + 0][ak] = v.x; sAT[aj + 1][ak] = v.y;
            sAT[aj + 2][ak] = v.z; sAT[aj + 3][ak] = v.w;
        }
        {
            // x transpose: thread t owns column d = d0 + t
            const float4* xs = (const float4*)(xb + (size_t)(d0 + t) * NN + n0);
            float4 v0 = xs[0], v1 = xs[1], v2 = xs[2], v3 = xs[3];
            sXT[ 0][t] = v0.x; sXT[ 1][t] = v0.y; sXT[ 2][t] = v0.z; sXT[ 3][t] = v0.w;
            sXT[ 4][t] = v1.x; sXT[ 5][t] = v1.y; sXT[ 6][t] = v1.z; sXT[ 7][t] = v1.w;
            sXT[ 8][t] = v2.x; sXT[ 9][t] = v2.y; sXT[10][t] = v2.z; sXT[11][t] = v2.w;
            sXT[12][t] = v3.x; sXT[13][t] = v3.y; sXT[14][t] = v3.z; sXT[15][t] = v3.w;
        }
        __syncthreads();
#pragma unroll
        for (int nn = 0; nn < 16; nn++) {
            float4 ka = *(const float4*)&sAT[nn][ty * 8];
            float4 kb = *(const float4*)&sAT[nn][ty * 8 + 4];
            float4 x0 = *(const float4*)&sXT[nn][tx * 8];
            float4 x1 = *(const float4*)&sXT[nn][tx * 8 + 4];
            unsigned long long xp0 = pack2(x0.x, x0.y);
            unsigned long long xp1 = pack2(x0.z, x0.w);
            unsigned long long xp2 = pack2(x1.x, x1.y);
            unsigned long long xp3 = pack2(x1.z, x1.w);
            float kf[8] = {ka.x, ka.y, ka.z, ka.w, kb.x, kb.y, kb.z, kb.w};
#pragma unroll
            for (int i = 0; i < 8; i++) {
                unsigned long long kp = pack2(kf[i], kf[i]);
                ffma2(acc[i][0], kp, xp0);
                ffma2(acc[i][1], kp, xp1);
                ffma2(acc[i][2], kp, xp2);
                ffma2(acc[i][3], kp, xp3);
            }
        }
        __syncthreads();
    }

    // epilogue: V = C - 32*c ; per-d sum of V^2 over k
    float v[8][8];
    float p[8] = {0.f, 0.f, 0.f, 0.f, 0.f, 0.f, 0.f, 0.f};
#pragma unroll
    for (int i = 0; i < 8; i++) {
        const int k = ty * 8 + i;
        const float* cp = c + (size_t)k * DD + d0 + tx * 8;
        float4 c0 = *(const float4*)cp;
        float4 c1 = *(const float4*)(cp + 4);
        float2 u0 = unpack2(acc[i][0]);
        float2 u1 = unpack2(acc[i][1]);
        float2 u2 = unpack2(acc[i][2]);
        float2 u3 = unpack2(acc[i][3]);
        v[i][0] = u0.x - 32.f * c0.x;
        v[i][1] = u0.y - 32.f * c0.y;
        v[i][2] = u1.x - 32.f * c0.z;
        v[i][3] = u1.y - 32.f * c0.w;
        v[i][4] = u2.x - 32.f * c1.x;
        v[i][5] = u2.y - 32.f * c1.y;
        v[i][6] = u3.x - 32.f * c1.z;
        v[i][7] = u3.y - 32.f * c1.w;
#pragma unroll
        for (int j = 0; j < 8; j++) p[j] += v[i][j] * v[i][j];
    }
    *(float4*)&red[ty][tx * 8]     = make_float4(p[0], p[1], p[2], p[3]);
    *(float4*)&red[ty][tx * 8 + 4] = make_float4(p[4], p[5], p[6], p[7]);
    __syncthreads();

    {
        float s = 0.f;
#pragma unroll
        for (int q = 0; q < 8; q++) s += red[q][t];
        float n1 = fmaxf(sqrtf(s), EPSN);
        float n2 = fmaxf(sqrtf(s) / n1, EPSN);
        sinv[t] = 1.0f / (n1 * n2);
    }
    __syncthreads();

#pragma unroll
    for (int j = 0; j < 8; j++) {
        float s = sinv[tx * 8 + j];
        float* dst = g_v + ((size_t)b * DD + d0 + tx * 8 + j) * KK + ty * 8;
        *(float4*)dst       = make_float4(v[0][j] * s, v[1][j] * s, v[2][j] * s, v[3][j] * s);
        *(float4*)(dst + 4) = make_float4(v[4][j] * s, v[5][j] * s, v[6][j] * s, v[7][j] * s);
    }
}

// ============================================================================
// Kernel 4: transpose g_v [b][dk] -> out [dk][b]
// ============================================================================
__global__ __launch_bounds__(256) void k_tr(float* __restrict__ out) {
    __shared__ float tile[32][33];
    const int bx = blockIdx.x * 32;   // dk
    const int by = blockIdx.y * 32;   // b
    const int tx = threadIdx.x & 31;
    const int ty = threadIdx.x >> 5;  // 0..7

#pragma unroll
    for (int i = 0; i < 32; i += 8)
        tile[ty + i][tx] = g_v[(size_t)(by + ty + i) * (DD * KK) + bx + tx];
    __syncthreads();
#pragma unroll
    for (int i = 0; i < 32; i += 8)
        out[(size_t)(bx + ty + i) * BB + by + tx] = tile[tx][ty + i];
}

// ============================================================================
extern "C" void kernel_launch(void* const* d_in, const int* in_sizes, int n_in,
                              void* d_out, int out_size) {
    const float* x  = (const float*)d_in[0];
    const float* wt = (const float*)d_in[1];
    const float* c  = (const float*)d_in[2];
    float* out = (float*)d_out;

    k_features<<<dim3(NN / 256, BB), 256>>>(x, wt);

    k_softmax<<<BB * KK, 256>>>();

    k_vlad<<<dim3(DD / 256, BB), 256>>>(x, c);

    k_tr<<<dim3(DD * KK / 32, BB / 32), 256>>>(out);
}

// round 7
// speedup vs baseline: 1.4070x; 1.4070x over previous
#include <cuda_runtime.h>
#include <cstdint>

// NetVladCNN: B=64, D=512, H=W=32 (N=1024), K=64
// x: (B,D,H,W) fp32   w: (K,D)   c: (K,D)   out: (D,K,B) fp32
//
// Stage 1 (mma.sync tf32 split): features[b,k,n] = sum_d w[k,d]*x[b,d,n]
// Stage 2: softmax over h (sum_n a == 32 exactly)
// Stage 3 (mma.sync tf32 split): C[d,k] = sum_n x[d,n]*a[k,n]; V = C - 32*c^T;
//         warp-local k-normalize; write g_v[b][d][k]
// Stage 4: transpose g_v [b][dk] -> out [dk][b]

#define BB 64
#define DD 512
#define NN 1024
#define KK 64
#define EPSN 1e-12f

__device__ float g_a[(size_t)BB * KK * NN];   // features / softmaxed a [b][k][n]
__device__ float g_v[(size_t)BB * DD * KK];   // normalized V [b][d][k]

// ---------- tf32 mma helpers ----------
__device__ __forceinline__ void mma8(float* c, const uint32_t* a, uint32_t b0,
                                     uint32_t b1) {
    asm volatile(
        "mma.sync.aligned.m16n8k8.row.col.f32.tf32.tf32.f32 "
        "{%0,%1,%2,%3}, {%4,%5,%6,%7}, {%8,%9}, {%0,%1,%2,%3};"
        : "+f"(c[0]), "+f"(c[1]), "+f"(c[2]), "+f"(c[3])
        : "r"(a[0]), "r"(a[1]), "r"(a[2]), "r"(a[3]), "r"(b0), "r"(b1));
}
__device__ __forceinline__ uint32_t hi_tf32(float x) {
    return __float_as_uint(x) & 0xFFFFE000u;
}
__device__ __forceinline__ uint32_t lo_tf32(float x) {
    float h = __uint_as_float(__float_as_uint(x) & 0xFFFFE000u);
    return __float_as_uint(x - h) & 0xFFFFE000u;
}

// ============================================================================
// Kernel 1: features GEMM (tf32 mma, 2-term split).
// Per b: M=64 (k), N'=256 (n tile), contraction d=512 in chunks of 32.
// 256 thr = 8 warps; warp tile = m32 x n64 (2 m-tiles x 8 n-frags).
// ============================================================================
__global__ __launch_bounds__(256, 2) void k_feat(const float* __restrict__ x,
                                                 const float* __restrict__ wt) {
    __shared__ float sW[64][36];    // w tile [k][d32] (+pad)
    __shared__ float sX[32][264];   // x tile [d32][n256] (+pad)

    const int b = blockIdx.y, n0 = blockIdx.x * 256;
    const int t = threadIdx.x, lane = t & 31, warp = t >> 5;
    const int g = lane >> 2, tq = lane & 3;
    const int k0 = (warp >> 2) * 32;     // warp m-base (k)
    const int nb = (warp & 3) * 64;      // warp n-base
    const float* xb = x + (size_t)b * DD * NN;

    float acc[2][8][4];
#pragma unroll
    for (int i = 0; i < 2; i++)
#pragma unroll
        for (int j = 0; j < 8; j++)
#pragma unroll
            for (int r = 0; r < 4; r++) acc[i][j][r] = 0.f;

    const int wrow = t & 63, wcg = t >> 6;      // w loader
    const int xrow = t >> 3, xc = (t & 7) * 4;  // x loader

    for (int d0 = 0; d0 < DD; d0 += 32) {
        {
            float4 w0 = *(const float4*)(wt + (size_t)wrow * DD + d0 + wcg * 8);
            float4 w1 = *(const float4*)(wt + (size_t)wrow * DD + d0 + wcg * 8 + 4);
            *(float4*)&sW[wrow][wcg * 8] = w0;
            *(float4*)&sW[wrow][wcg * 8 + 4] = w1;
        }
#pragma unroll
        for (int i = 0; i < 8; i++) {
            float4 v = *(const float4*)(xb + (size_t)(d0 + xrow) * NN + n0 + xc + i * 32);
            *(float4*)&sX[xrow][xc + i * 32] = v;
        }
        __syncthreads();

#pragma unroll
        for (int s = 0; s < 4; s++) {
            const int dl = s * 8;
            uint32_t ah[2][4], al[2][4];
#pragma unroll
            for (int mi = 0; mi < 2; mi++) {
                float a0 = sW[k0 + mi * 16 + g][dl + tq];
                float a1 = sW[k0 + mi * 16 + g + 8][dl + tq];
                float a2 = sW[k0 + mi * 16 + g][dl + tq + 4];
                float a3 = sW[k0 + mi * 16 + g + 8][dl + tq + 4];
                ah[mi][0] = hi_tf32(a0); al[mi][0] = lo_tf32(a0);
                ah[mi][1] = hi_tf32(a1); al[mi][1] = lo_tf32(a1);
                ah[mi][2] = hi_tf32(a2); al[mi][2] = lo_tf32(a2);
                ah[mi][3] = hi_tf32(a3); al[mi][3] = lo_tf32(a3);
            }
#pragma unroll
            for (int j = 0; j < 8; j++) {
                float b0 = sX[dl + tq][nb + j * 8 + g];
                float b1 = sX[dl + tq + 4][nb + j * 8 + g];
                uint32_t bh0 = hi_tf32(b0), bl0 = lo_tf32(b0);
                uint32_t bh1 = hi_tf32(b1), bl1 = lo_tf32(b1);
#pragma unroll
                for (int mi = 0; mi < 2; mi++) {
                    mma8(acc[mi][j], ah[mi], bh0, bh1);
                    mma8(acc[mi][j], ah[mi], bl0, bl1);
                    mma8(acc[mi][j], al[mi], bh0, bh1);
                }
            }
        }
        __syncthreads();
    }

#pragma unroll
    for (int mi = 0; mi < 2; mi++) {
#pragma unroll
        for (int j = 0; j < 8; j++) {
            const int k = k0 + mi * 16 + g;
            const int n = n0 + nb + j * 8 + 2 * tq;
            *(float2*)&g_a[((size_t)b * KK + k) * NN + n] =
                make_float2(acc[mi][j][0], acc[mi][j][1]);
            *(float2*)&g_a[((size_t)b * KK + k + 8) * NN + n] =
                make_float2(acc[mi][j][2], acc[mi][j][3]);
        }
    }
}

// ============================================================================
// Kernel 2: softmax over h, per (b,k) row of 1024 = 32h x 32w.
// ============================================================================
__global__ __launch_bounds__(256) void k_softmax() {
    __shared__ float red[8][33];
    const size_t base = (size_t)blockIdx.x * NN;
    const int t = threadIdx.x;
    const int q = t >> 5, w = t & 31;

    float v[4];
#pragma unroll
    for (int u = 0; u < 4; u++) v[u] = g_a[base + t + 256 * u];

    float m = fmaxf(fmaxf(v[0], v[1]), fmaxf(v[2], v[3]));
    red[q][w] = m;
    __syncthreads();
    float mm = red[0][w];
#pragma unroll
    for (int qq = 1; qq < 8; qq++) mm = fmaxf(mm, red[qq][w]);
    __syncthreads();

    float s = 0.f;
#pragma unroll
    for (int u = 0; u < 4; u++) { v[u] = __expf(v[u] - mm); s += v[u]; }
    red[q][w] = s;
    __syncthreads();
    float ss = red[0][w];
#pragma unroll
    for (int qq = 1; qq < 8; qq++) ss += red[qq][w];

    float inv = 1.0f / ss;
#pragma unroll
    for (int u = 0; u < 4; u++) g_a[base + t + 256 * u] = v[u] * inv;
}

// ============================================================================
// Kernel 3: V GEMM (tf32 mma, 2-term split), output-flipped C[d,k].
// Per b: M=128 (d tile), N'=64 (all k), contraction n=1024 in chunks of 32.
// 256 thr = 8 warps; warp tile = m16(d) x n64(k) = 8 k-frags.
// A = x[d][n] (n contig), B = a[k][n] (col-major, n contig) -> no transposes.
// Epilogue: V = C - 32*c^T; warp-local L2 norm over k; write g_v[b][d][k].
// ============================================================================
__global__ __launch_bounds__(256, 2) void k_vlad(const float* __restrict__ x,
                                                 const float* __restrict__ cc) {
    __shared__ float sA[64][36];    // a tile [k64][n32]
    __shared__ float sX[128][36];   // x tile [d128][n32]

    const int b = blockIdx.y, d0 = blockIdx.x * 128;
    const int t = threadIdx.x, lane = t & 31, warp = t >> 5;
    const int g = lane >> 2, tq = lane & 3;
    const int m0 = warp * 16;       // warp d-base within tile
    const float* xb = x + (size_t)b * DD * NN;
    const float* ab = g_a + (size_t)b * KK * NN;

    float acc[8][4];
#pragma unroll
    for (int j = 0; j < 8; j++)
#pragma unroll
        for (int r = 0; r < 4; r++) acc[j][r] = 0.f;

    const int arow = t & 63, acg = t >> 6;        // a loader
    const int xrow = t >> 1, xch = (t & 1) * 16;  // x loader

    for (int n0 = 0; n0 < NN; n0 += 32) {
        {
            float4 a0 = *(const float4*)(ab + (size_t)arow * NN + n0 + acg * 8);
            float4 a1 = *(const float4*)(ab + (size_t)arow * NN + n0 + acg * 8 + 4);
            *(float4*)&sA[arow][acg * 8] = a0;
            *(float4*)&sA[arow][acg * 8 + 4] = a1;
        }
#pragma unroll
        for (int i = 0; i < 4; i++) {
            float4 v = *(const float4*)(xb + (size_t)(d0 + xrow) * NN + n0 + xch + i * 4);
            *(float4*)&sX[xrow][xch + i * 4] = v;
        }
        __syncthreads();

#pragma unroll
        for (int s = 0; s < 4; s++) {
            const int nl = s * 8;
            float a0 = sX[m0 + g][nl + tq];
            float a1 = sX[m0 + g + 8][nl + tq];
            float a2 = sX[m0 + g][nl + tq + 4];
            float a3 = sX[m0 + g + 8][nl + tq + 4];
            uint32_t ah[4] = {hi_tf32(a0), hi_tf32(a1), hi_tf32(a2), hi_tf32(a3)};
            uint32_t al[4] = {lo_tf32(a0), lo_tf32(a1), lo_tf32(a2), lo_tf32(a3)};
#pragma unroll
            for (int j = 0; j < 8; j++) {
                float b0 = sA[j * 8 + g][nl + tq];
                float b1 = sA[j * 8 + g][nl + tq + 4];
                uint32_t bh0 = hi_tf32(b0), bl0 = lo_tf32(b0);
                uint32_t bh1 = hi_tf32(b1), bl1 = lo_tf32(b1);
                mma8(acc[j], ah, bh0, bh1);
                mma8(acc[j], ah, bl0, bl1);
                mma8(acc[j], al, bh0, bh1);
            }
        }
        __syncthreads();
    }

    // epilogue: rows d = d0+m0+g (half 0) and +8 (half 1); cols k = j*8+2tq(+1)
#pragma unroll
    for (int half = 0; half < 2; half++) {
        const int d = d0 + m0 + g + half * 8;
        float v[16];
        float s = 0.f;
#pragma unroll
        for (int j = 0; j < 8; j++) {
            const int k = j * 8 + 2 * tq;
            float c0 = cc[(size_t)k * DD + d];
            float c1 = cc[(size_t)(k + 1) * DD + d];
            float v0 = acc[j][half * 2 + 0] - 32.f * c0;
            float v1 = acc[j][half * 2 + 1] - 32.f * c1;
            v[j * 2] = v0; v[j * 2 + 1] = v1;
            s += v0 * v0 + v1 * v1;
        }
        s += __shfl_xor_sync(0xffffffffu, s, 1);
        s += __shfl_xor_sync(0xffffffffu, s, 2);
        float n1 = fmaxf(sqrtf(s), EPSN);
        float n2 = fmaxf(sqrtf(s) / n1, EPSN);
        float inv = 1.0f / (n1 * n2);
        float* dst = g_v + ((size_t)b * DD + d) * KK;
#pragma unroll
        for (int j = 0; j < 8; j++)
            *(float2*)(dst + j * 8 + 2 * tq) =
                make_float2(v[j * 2] * inv, v[j * 2 + 1] * inv);
    }
}

// ============================================================================
// Kernel 4: transpose g_v [b][dk] -> out [dk][b]
// ============================================================================
__global__ __launch_bounds__(256) void k_tr(float* __restrict__ out) {
    __shared__ float tile[32][33];
    const int bx = blockIdx.x * 32;   // dk
    const int by = blockIdx.y * 32;   // b
    const int tx = threadIdx.x & 31;
    const int ty = threadIdx.x >> 5;  // 0..7

#pragma unroll
    for (int i = 0; i < 32; i += 8)
        tile[ty + i][tx] = g_v[(size_t)(by + ty + i) * (DD * KK) + bx + tx];
    __syncthreads();
#pragma unroll
    for (int i = 0; i < 32; i += 8)
        out[(size_t)(bx + ty + i) * BB + by + tx] = tile[tx][ty + i];
}

// ============================================================================
extern "C" void kernel_launch(void* const* d_in, const int* in_sizes, int n_in,
                              void* d_out, int out_size) {
    const float* x  = (const float*)d_in[0];
    const float* wt = (const float*)d_in[1];
    const float* c  = (const float*)d_in[2];
    float* out = (float*)d_out;

    k_feat<<<dim3(NN / 256, BB), 256>>>(x, wt);

    k_softmax<<<BB * KK, 256>>>();

    k_vlad<<<dim3(DD / 128, BB), 256>>>(x, c);

    k_tr<<<dim3(DD * KK / 32, BB / 32), 256>>>(out);
}

// round 8
// speedup vs baseline: 1.6432x; 1.1679x over previous
#include <cuda_runtime.h>
#include <cstdint>

// NetVladCNN: B=64, D=512, H=W=32 (N=1024), K=64
// x: (B,D,H,W) fp32   w: (K,D)   c: (K,D)   out: (D,K,B) fp32
//
// Stage 1 (mma.sync bf16 m16n8k16, 3-term split): features = w·x
// Stage 2: softmax over h (sum_n a == 32 exactly)
// Stage 3 (mma.sync bf16, 3-term split): C[d,k] = sum_n x[d,n]*a[k,n];
//         V = C - 32*c^T; warp-local k-normalize; g_v[b][d][k]
// Stage 4: transpose g_v [b][dk] -> out [dk][b]

#define BB 64
#define DD 512
#define NN 1024
#define KK 64
#define EPSN 1e-12f

__device__ float g_a[(size_t)BB * KK * NN];   // features / softmaxed a [b][k][n]
__device__ float g_v[(size_t)BB * DD * KK];   // normalized V [b][d][k]

// ---------- bf16 mma helpers ----------
__device__ __forceinline__ void mma16(float* c, const uint32_t* a, uint32_t b0,
                                      uint32_t b1) {
    asm volatile(
        "mma.sync.aligned.m16n8k16.row.col.f32.bf16.bf16.f32 "
        "{%0,%1,%2,%3}, {%4,%5,%6,%7}, {%8,%9}, {%0,%1,%2,%3};"
        : "+f"(c[0]), "+f"(c[1]), "+f"(c[2]), "+f"(c[3])
        : "r"(a[0]), "r"(a[1]), "r"(a[2]), "r"(a[3]), "r"(b0), "r"(b1));
}

// split a float pair (f0 = even k, f1 = odd k) into hi/lo bf16x2 regs.
// hi = truncated top-16 bits (exact bf16); lo = rn(f - hi).
__device__ __forceinline__ void split2s(float f0, float f1, uint32_t& h,
                                        uint32_t& l) {
    uint32_t u0 = __float_as_uint(f0), u1 = __float_as_uint(f1);
    asm("prmt.b32 %0, %1, %2, 0x7632;" : "=r"(h) : "r"(u0), "r"(u1));
    float l0 = f0 - __uint_as_float(u0 & 0xFFFF0000u);
    float l1 = f1 - __uint_as_float(u1 & 0xFFFF0000u);
    asm("cvt.rn.bf16x2.f32 %0, %1, %2;" : "=r"(l) : "f"(l1), "f"(l0));
}
__device__ __forceinline__ void split2(float2 f, uint32_t& h, uint32_t& l) {
    split2s(f.x, f.y, h, l);
}

// ============================================================================
// Kernel 1: features GEMM (bf16 split mma).
// Per b: M=64 (k), N'=256 (n tile), contraction d=512 in chunks of 32 (2 k16).
// 256 thr = 8 warps; warp tile = m32 x n64 (2 m-tiles x 8 n-frags).
// ============================================================================
__global__ __launch_bounds__(256, 2) void k_feat(const float* __restrict__ x,
                                                 const float* __restrict__ wt) {
    __shared__ float sW[64][36];    // w tile [k][d32] (+pad)
    __shared__ float sX[32][264];   // x tile [d32][n256] (+pad)

    const int b = blockIdx.y, n0 = blockIdx.x * 256;
    const int t = threadIdx.x, lane = t & 31, warp = t >> 5;
    const int g = lane >> 2, tq = lane & 3;
    const int k0 = (warp >> 2) * 32;     // warp m-base (k)
    const int nb = (warp & 3) * 64;      // warp n-base
    const float* xb = x + (size_t)b * DD * NN;

    float acc[2][8][4];
#pragma unroll
    for (int i = 0; i < 2; i++)
#pragma unroll
        for (int j = 0; j < 8; j++)
#pragma unroll
            for (int r = 0; r < 4; r++) acc[i][j][r] = 0.f;

    const int wrow = t & 63, wcg = t >> 6;      // w loader
    const int xrow = t >> 3, xc = (t & 7) * 4;  // x loader

    for (int d0 = 0; d0 < DD; d0 += 32) {
        {
            float4 w0 = *(const float4*)(wt + (size_t)wrow * DD + d0 + wcg * 8);
            float4 w1 = *(const float4*)(wt + (size_t)wrow * DD + d0 + wcg * 8 + 4);
            *(float4*)&sW[wrow][wcg * 8] = w0;
            *(float4*)&sW[wrow][wcg * 8 + 4] = w1;
        }
#pragma unroll
        for (int i = 0; i < 8; i++) {
            float4 v = *(const float4*)(xb + (size_t)(d0 + xrow) * NN + n0 + xc + i * 32);
            *(float4*)&sX[xrow][xc + i * 32] = v;
        }
        __syncthreads();

#pragma unroll
        for (int s = 0; s < 2; s++) {
            const int dl = s * 16;
            uint32_t ah[2][4], al[2][4];
#pragma unroll
            for (int mi = 0; mi < 2; mi++) {
                const int r0 = k0 + mi * 16 + g;
                float2 a0 = *(const float2*)&sW[r0][dl + 2 * tq];
                float2 a1 = *(const float2*)&sW[r0 + 8][dl + 2 * tq];
                float2 a2 = *(const float2*)&sW[r0][dl + 2 * tq + 8];
                float2 a3 = *(const float2*)&sW[r0 + 8][dl + 2 * tq + 8];
                split2(a0, ah[mi][0], al[mi][0]);
                split2(a1, ah[mi][1], al[mi][1]);
                split2(a2, ah[mi][2], al[mi][2]);
                split2(a3, ah[mi][3], al[mi][3]);
            }
#pragma unroll
            for (int j = 0; j < 8; j++) {
                const int n = nb + j * 8 + g;
                float b00 = sX[dl + 2 * tq][n];
                float b01 = sX[dl + 2 * tq + 1][n];
                float b10 = sX[dl + 2 * tq + 8][n];
                float b11 = sX[dl + 2 * tq + 9][n];
                uint32_t bh0, bl0, bh1, bl1;
                split2s(b00, b01, bh0, bl0);
                split2s(b10, b11, bh1, bl1);
#pragma unroll
                for (int mi = 0; mi < 2; mi++) {
                    mma16(acc[mi][j], ah[mi], bh0, bh1);
                    mma16(acc[mi][j], ah[mi], bl0, bl1);
                    mma16(acc[mi][j], al[mi], bh0, bh1);
                }
            }
        }
        __syncthreads();
    }

#pragma unroll
    for (int mi = 0; mi < 2; mi++) {
#pragma unroll
        for (int j = 0; j < 8; j++) {
            const int k = k0 + mi * 16 + g;
            const int n = n0 + nb + j * 8 + 2 * tq;
            *(float2*)&g_a[((size_t)b * KK + k) * NN + n] =
                make_float2(acc[mi][j][0], acc[mi][j][1]);
            *(float2*)&g_a[((size_t)b * KK + k + 8) * NN + n] =
                make_float2(acc[mi][j][2], acc[mi][j][3]);
        }
    }
}

// ============================================================================
// Kernel 2: softmax over h, per (b,k) row of 1024 = 32h x 32w.
// ============================================================================
__global__ __launch_bounds__(256) void k_softmax() {
    __shared__ float red[8][33];
    const size_t base = (size_t)blockIdx.x * NN;
    const int t = threadIdx.x;
    const int q = t >> 5, w = t & 31;

    float v[4];
#pragma unroll
    for (int u = 0; u < 4; u++) v[u] = g_a[base + t + 256 * u];

    float m = fmaxf(fmaxf(v[0], v[1]), fmaxf(v[2], v[3]));
    red[q][w] = m;
    __syncthreads();
    float mm = red[0][w];
#pragma unroll
    for (int qq = 1; qq < 8; qq++) mm = fmaxf(mm, red[qq][w]);
    __syncthreads();

    float s = 0.f;
#pragma unroll
    for (int u = 0; u < 4; u++) { v[u] = __expf(v[u] - mm); s += v[u]; }
    red[q][w] = s;
    __syncthreads();
    float ss = red[0][w];
#pragma unroll
    for (int qq = 1; qq < 8; qq++) ss += red[qq][w];

    float inv = 1.0f / ss;
#pragma unroll
    for (int u = 0; u < 4; u++) g_a[base + t + 256 * u] = v[u] * inv;
}

// ============================================================================
// Kernel 3: V GEMM (bf16 split mma), output-flipped C[d,k].
// Per b: M=128 (d tile), N'=64 (all k), contraction n=1024 in chunks of 32.
// 256 thr = 8 warps; warp tile = m16(d) x n64(k) = 8 k-frags.
// A = x[d][n] (n contig), B = a[k][n] (col-major, n contig) -> all float2 LDS.
// Epilogue: V = C - 32*c^T; warp-local L2 norm over k; write g_v[b][d][k].
// ============================================================================
__global__ __launch_bounds__(256, 2) void k_vlad(const float* __restrict__ x,
                                                 const float* __restrict__ cc) {
    __shared__ float sA[64][36];    // a tile [k64][n32]
    __shared__ float sX[128][36];   // x tile [d128][n32]

    const int b = blockIdx.y, d0 = blockIdx.x * 128;
    const int t = threadIdx.x, lane = t & 31, warp = t >> 5;
    const int g = lane >> 2, tq = lane & 3;
    const int m0 = warp * 16;       // warp d-base within tile
    const float* xb = x + (size_t)b * DD * NN;
    const float* ab = g_a + (size_t)b * KK * NN;

    float acc[8][4];
#pragma unroll
    for (int j = 0; j < 8; j++)
#pragma unroll
        for (int r = 0; r < 4; r++) acc[j][r] = 0.f;

    const int arow = t & 63, acg = t >> 6;        // a loader
    const int xrow = t >> 1, xch = (t & 1) * 16;  // x loader

    for (int n0 = 0; n0 < NN; n0 += 32) {
        {
            float4 a0 = *(const float4*)(ab + (size_t)arow * NN + n0 + acg * 8);
            float4 a1 = *(const float4*)(ab + (size_t)arow * NN + n0 + acg * 8 + 4);
            *(float4*)&sA[arow][acg * 8] = a0;
            *(float4*)&sA[arow][acg * 8 + 4] = a1;
        }
#pragma unroll
        for (int i = 0; i < 4; i++) {
            float4 v = *(const float4*)(xb + (size_t)(d0 + xrow) * NN + n0 + xch + i * 4);
            *(float4*)&sX[xrow][xch + i * 4] = v;
        }
        __syncthreads();

#pragma unroll
        for (int s = 0; s < 2; s++) {
            const int nl = s * 16;
            float2 a0 = *(const float2*)&sX[m0 + g][nl + 2 * tq];
            float2 a1 = *(const float2*)&sX[m0 + g + 8][nl + 2 * tq];
            float2 a2 = *(const float2*)&sX[m0 + g][nl + 2 * tq + 8];
            float2 a3 = *(const float2*)&sX[m0 + g + 8][nl + 2 * tq + 8];
            uint32_t ah[4], al[4];
            split2(a0, ah[0], al[0]);
            split2(a1, ah[1], al[1]);
            split2(a2, ah[2], al[2]);
            split2(a3, ah[3], al[3]);
#pragma unroll
            for (int j = 0; j < 8; j++) {
                const int kc = j * 8 + g;
                float2 b0 = *(const float2*)&sA[kc][nl + 2 * tq];
                float2 b1 = *(const float2*)&sA[kc][nl + 2 * tq + 8];
                uint32_t bh0, bl0, bh1, bl1;
                split2(b0, bh0, bl0);
                split2(b1, bh1, bl1);
                mma16(acc[j], ah, bh0, bh1);
                mma16(acc[j], ah, bl0, bl1);
                mma16(acc[j], al, bh0, bh1);
            }
        }
        __syncthreads();
    }

    // epilogue: rows d = d0+m0+g (half 0) and +8 (half 1); cols k = j*8+2tq(+1)
#pragma unroll
    for (int half = 0; half < 2; half++) {
        const int d = d0 + m0 + g + half * 8;
        float v[16];
        float s = 0.f;
#pragma unroll
        for (int j = 0; j < 8; j++) {
            const int k = j * 8 + 2 * tq;
            float c0 = cc[(size_t)k * DD + d];
            float c1 = cc[(size_t)(k + 1) * DD + d];
            float v0 = acc[j][half * 2 + 0] - 32.f * c0;
            float v1 = acc[j][half * 2 + 1] - 32.f * c1;
            v[j * 2] = v0; v[j * 2 + 1] = v1;
            s += v0 * v0 + v1 * v1;
        }
        s += __shfl_xor_sync(0xffffffffu, s, 1);
        s += __shfl_xor_sync(0xffffffffu, s, 2);
        float n1 = fmaxf(sqrtf(s), EPSN);
        float n2 = fmaxf(sqrtf(s) / n1, EPSN);
        float inv = 1.0f / (n1 * n2);
        float* dst = g_v + ((size_t)b * DD + d) * KK;
#pragma unroll
        for (int j = 0; j < 8; j++)
            *(float2*)(dst + j * 8 + 2 * tq) =
                make_float2(v[j * 2] * inv, v[j * 2 + 1] * inv);
    }
}

// ============================================================================
// Kernel 4: transpose g_v [b][dk] -> out [dk][b]
// ============================================================================
__global__ __launch_bounds__(256) void k_tr(float* __restrict__ out) {
    __shared__ float tile[32][33];
    const int bx = blockIdx.x * 32;   // dk
    const int by = blockIdx.y * 32;   // b
    const int tx = threadIdx.x & 31;
    const int ty = threadIdx.x >> 5;  // 0..7

#pragma unroll
    for (int i = 0; i < 32; i += 8)
        tile[ty + i][tx] = g_v[(size_t)(by + ty + i) * (DD * KK) + bx + tx];
    __syncthreads();
#pragma unroll
    for (int i = 0; i < 32; i += 8)
        out[(size_t)(bx + ty + i) * BB + by + tx] = tile[tx][ty + i];
}

// ============================================================================
extern "C" void kernel_launch(void* const* d_in, const int* in_sizes, int n_in,
                              void* d_out, int out_size) {
    const float* x  = (const float*)d_in[0];
    const float* wt = (const float*)d_in[1];
    const float* c  = (const float*)d_in[2];
    float* out = (float*)d_out;

    k_feat<<<dim3(NN / 256, BB), 256>>>(x, wt);

    k_softmax<<<BB * KK, 256>>>();

    k_vlad<<<dim3(DD / 128, BB), 256>>>(x, c);

    k_tr<<<dim3(DD * KK / 32, BB / 32), 256>>>(out);
}

// round 10
// speedup vs baseline: 1.8643x; 1.1345x over previous
#include <cuda_runtime.h>
#include <cstdint>

// NetVladCNN: B=64, D=512, H=W=32 (N=1024), K=64
// x: (B,D,H,W) fp32   w: (K,D)   c: (K,D)   out: (D,K,B) fp32
//
// Stage 1 (bf16 m16n8k16 mma, 3-term split, split-at-store): features = w·x
// Stage 2: softmax over h (sum_n a == 32 exactly)
// Stage 3 (bf16 split mma, split-at-store): C[d,k] = sum_n x[d,n]*a[k,n];
//         V = C - 32*c^T; warp-local k-normalize; g_v[b][d][k]
// Stage 4: transpose g_v [b][dk] -> out [dk][b]

#define BB 64
#define DD 512
#define NN 1024
#define KK 64
#define EPSN 1e-12f

__device__ float g_a[(size_t)BB * KK * NN];   // features / softmaxed a [b][k][n]
__device__ float g_v[(size_t)BB * DD * KK];   // normalized V [b][d][k]

// ---------- bf16 mma helpers ----------
__device__ __forceinline__ void mma16(float* c, const uint32_t* a, uint32_t b0,
                                      uint32_t b1) {
    asm volatile(
        "mma.sync.aligned.m16n8k16.row.col.f32.bf16.bf16.f32 "
        "{%0,%1,%2,%3}, {%4,%5,%6,%7}, {%8,%9}, {%0,%1,%2,%3};"
        : "+f"(c[0]), "+f"(c[1]), "+f"(c[2]), "+f"(c[3])
        : "r"(a[0]), "r"(a[1]), "r"(a[2]), "r"(a[3]), "r"(b0), "r"(b1));
}

// split a contraction pair (e = even k, o = odd k) into hi/lo bf16x2.
// hi = exact top-16 truncation; lo = rn(f - hi). lo half of reg = even k.
__device__ __forceinline__ void splitp(float e, float o, uint32_t& h,
                                       uint32_t& l) {
    uint32_t ue = __float_as_uint(e), uo = __float_as_uint(o);
    asm("prmt.b32 %0, %1, %2, 0x7632;" : "=r"(h) : "r"(ue), "r"(uo));
    float le = e - __uint_as_float(ue & 0xFFFF0000u);
    float lo_ = o - __uint_as_float(uo & 0xFFFF0000u);
    asm("cvt.rn.bf16x2.f32 %0, %1, %2;" : "=r"(l) : "f"(lo_), "f"(le));
}

// ============================================================================
// Kernel 1: features GEMM (bf16 split, packed tiles).
// Per b: M=64 (k), N'=256 (n tile), contraction d=512 in chunks of 32.
// 256 thr = 8 warps; warp tile = m32 x n64 (2 m-tiles x 8 n-frags).
// ============================================================================
#define WPAD 20
#define XPAD 264
__global__ __launch_bounds__(256, 2) void k_feat(const float* __restrict__ x,
                                                 const float* __restrict__ wt) {
    __shared__ uint32_t sWh[64][WPAD], sWl[64][WPAD];   // [k][d-pair 16]
    __shared__ uint32_t sXh[16][XPAD], sXl[16][XPAD];   // [d-pair][n 256]

    const int b = blockIdx.y, n0 = blockIdx.x * 256;
    const int t = threadIdx.x, lane = t & 31, warp = t >> 5;
    const int g = lane >> 2, tq = lane & 3;
    const int k0 = (warp >> 2) * 32;     // warp m-base (k)
    const int nb = (warp & 3) * 64;      // warp n-base
    const float* xb = x + (size_t)b * DD * NN;

    float acc[2][8][4];
#pragma unroll
    for (int i = 0; i < 2; i++)
#pragma unroll
        for (int j = 0; j < 8; j++)
#pragma unroll
            for (int r = 0; r < 4; r++) acc[i][j][r] = 0.f;

    const int wrow = t & 63, wseg = t >> 6;   // w loader: 4 segs x 8 d
    const int xdp = t >> 4, xtx = t & 15;     // x loader: d-pair row, col group

    for (int d0 = 0; d0 < DD; d0 += 32) {
        // ---- w tile: 64k x 32d -> 16 pairs, split at store ----
        {
            const float* src = wt + (size_t)wrow * DD + d0 + wseg * 8;
            float4 v0 = *(const float4*)src;
            float4 v1 = *(const float4*)(src + 4);
            uint32_t h, l;
            splitp(v0.x, v0.y, h, l); sWh[wrow][wseg * 4 + 0] = h; sWl[wrow][wseg * 4 + 0] = l;
            splitp(v0.z, v0.w, h, l); sWh[wrow][wseg * 4 + 1] = h; sWl[wrow][wseg * 4 + 1] = l;
            splitp(v1.x, v1.y, h, l); sWh[wrow][wseg * 4 + 2] = h; sWl[wrow][wseg * 4 + 2] = l;
            splitp(v1.z, v1.w, h, l); sWh[wrow][wseg * 4 + 3] = h; sWl[wrow][wseg * 4 + 3] = l;
        }
        // ---- x tile: 32d x 256n -> [16 dp][256 n], pairs across rows ----
        {
            const float* se = xb + (size_t)(d0 + 2 * xdp) * NN + n0;
            const float* so = se + NN;
#pragma unroll
            for (int q = 0; q < 4; q++) {
                const int col = xtx * 4 + 64 * q;
                float4 ve = *(const float4*)(se + col);
                float4 vo = *(const float4*)(so + col);
                uint32_t h0, l0, h1, l1, h2, l2, h3, l3;
                splitp(ve.x, vo.x, h0, l0);
                splitp(ve.y, vo.y, h1, l1);
                splitp(ve.z, vo.z, h2, l2);
                splitp(ve.w, vo.w, h3, l3);
                *(uint4*)&sXh[xdp][col] = make_uint4(h0, h1, h2, h3);
                *(uint4*)&sXl[xdp][col] = make_uint4(l0, l1, l2, l3);
            }
        }
        __syncthreads();

#pragma unroll
        for (int s = 0; s < 2; s++) {
            const int sp = s * 8;
            uint32_t ah[2][4], al[2][4];
#pragma unroll
            for (int mi = 0; mi < 2; mi++) {
                const int r0 = k0 + mi * 16 + g;
                ah[mi][0] = sWh[r0][sp + tq];     al[mi][0] = sWl[r0][sp + tq];
                ah[mi][1] = sWh[r0 + 8][sp + tq]; al[mi][1] = sWl[r0 + 8][sp + tq];
                ah[mi][2] = sWh[r0][sp + tq + 4];     al[mi][2] = sWl[r0][sp + tq + 4];
                ah[mi][3] = sWh[r0 + 8][sp + tq + 4]; al[mi][3] = sWl[r0 + 8][sp + tq + 4];
            }
#pragma unroll
            for (int j = 0; j < 8; j++) {
                const int n = nb + j * 8 + g;
                uint32_t bh0 = sXh[sp + tq][n], bl0 = sXl[sp + tq][n];
                uint32_t bh1 = sXh[sp + tq + 4][n], bl1 = sXl[sp + tq + 4][n];
#pragma unroll
                for (int mi = 0; mi < 2; mi++) {
                    mma16(acc[mi][j], ah[mi], bh0, bh1);
                    mma16(acc[mi][j], ah[mi], bl0, bl1);
                    mma16(acc[mi][j], al[mi], bh0, bh1);
                }
            }
        }
        __syncthreads();
    }

#pragma unroll
    for (int mi = 0; mi < 2; mi++) {
#pragma unroll
        for (int j = 0; j < 8; j++) {
            const int k = k0 + mi * 16 + g;
            const int n = n0 + nb + j * 8 + 2 * tq;
            *(float2*)&g_a[((size_t)b * KK + k) * NN + n] =
                make_float2(acc[mi][j][0], acc[mi][j][1]);
            *(float2*)&g_a[((size_t)b * KK + k + 8) * NN + n] =
                make_float2(acc[mi][j][2], acc[mi][j][3]);
        }
    }
}

// ============================================================================
// Kernel 2: softmax over h, per (b,k) row of 1024 = 32h x 32w.
// ============================================================================
__global__ __launch_bounds__(256) void k_softmax() {
    __shared__ float red[8][33];
    const size_t base = (size_t)blockIdx.x * NN;
    const int t = threadIdx.x;
    const int q = t >> 5, w = t & 31;

    float v[4];
#pragma unroll
    for (int u = 0; u < 4; u++) v[u] = g_a[base + t + 256 * u];

    float m = fmaxf(fmaxf(v[0], v[1]), fmaxf(v[2], v[3]));
    red[q][w] = m;
    __syncthreads();
    float mm = red[0][w];
#pragma unroll
    for (int qq = 1; qq < 8; qq++) mm = fmaxf(mm, red[qq][w]);
    __syncthreads();

    float s = 0.f;
#pragma unroll
    for (int u = 0; u < 4; u++) { v[u] = __expf(v[u] - mm); s += v[u]; }
    red[q][w] = s;
    __syncthreads();
    float ss = red[0][w];
#pragma unroll
    for (int qq = 1; qq < 8; qq++) ss += red[qq][w];

    float inv = 1.0f / ss;
#pragma unroll
    for (int u = 0; u < 4; u++) g_a[base + t + 256 * u] = v[u] * inv;
}

// ============================================================================
// Kernel 3: V GEMM (bf16 split, packed tiles), output-flipped C[d,k].
// Per b: M=128 (d tile), N'=64 (all k), contraction n=1024 in chunks of 32.
// 256 thr = 8 warps; warp tile = m16(d) x n64(k) = 8 k-frags.
// Epilogue: V = C - 32*c^T; warp-local L2 norm over k; write g_v[b][d][k].
// ============================================================================
__global__ __launch_bounds__(256, 2) void k_vlad(const float* __restrict__ x,
                                                 const float* __restrict__ cc) {
    __shared__ uint32_t sAh[64][WPAD], sAl[64][WPAD];     // [k][n-pair 16]
    __shared__ uint32_t sXh[128][WPAD], sXl[128][WPAD];   // [d][n-pair 16]

    const int b = blockIdx.y, d0 = blockIdx.x * 128;
    const int t = threadIdx.x, lane = t & 31, warp = t >> 5;
    const int g = lane >> 2, tq = lane & 3;
    const int m0 = warp * 16;       // warp d-base within tile
    const float* xb = x + (size_t)b * DD * NN;
    const float* ab = g_a + (size_t)b * KK * NN;

    float acc[8][4];
#pragma unroll
    for (int j = 0; j < 8; j++)
#pragma unroll
        for (int r = 0; r < 4; r++) acc[j][r] = 0.f;

    const int arow = t & 63, aseg = t >> 6;   // a loader: 4 segs x 8 n
    const int xrow = t >> 1, xseg = t & 1;    // x loader: 2 segs x 16 n

    for (int n0 = 0; n0 < NN; n0 += 32) {
        {
            const float* src = ab + (size_t)arow * NN + n0 + aseg * 8;
            float4 v0 = *(const float4*)src;
            float4 v1 = *(const float4*)(src + 4);
            uint32_t h0, l0, h1, l1, h2, l2, h3, l3;
            splitp(v0.x, v0.y, h0, l0);
            splitp(v0.z, v0.w, h1, l1);
            splitp(v1.x, v1.y, h2, l2);
            splitp(v1.z, v1.w, h3, l3);
            *(uint4*)&sAh[arow][aseg * 4] = make_uint4(h0, h1, h2, h3);
            *(uint4*)&sAl[arow][aseg * 4] = make_uint4(l0, l1, l2, l3);
        }
        {
            const float* src = xb + (size_t)(d0 + xrow) * NN + n0 + xseg * 16;
#pragma unroll
            for (int q = 0; q < 2; q++) {
                float4 v0 = *(const float4*)(src + q * 8);
                float4 v1 = *(const float4*)(src + q * 8 + 4);
                uint32_t h0, l0, h1, l1, h2, l2, h3, l3;
                splitp(v0.x, v0.y, h0, l0);
                splitp(v0.z, v0.w, h1, l1);
                splitp(v1.x, v1.y, h2, l2);
                splitp(v1.z, v1.w, h3, l3);
                *(uint4*)&sXh[xrow][xseg * 8 + q * 4] = make_uint4(h0, h1, h2, h3);
                *(uint4*)&sXl[xrow][xseg * 8 + q * 4] = make_uint4(l0, l1, l2, l3);
            }
        }
        __syncthreads();

#pragma unroll
        for (int s = 0; s < 2; s++) {
            const int sp = s * 8;
            uint32_t ah[4], al[4];
            ah[0] = sXh[m0 + g][sp + tq];     al[0] = sXl[m0 + g][sp + tq];
            ah[1] = sXh[m0 + g + 8][sp + tq]; al[1] = sXl[m0 + g + 8][sp + tq];
            ah[2] = sXh[m0 + g][sp + tq + 4];     al[2] = sXl[m0 + g][sp + tq + 4];
            ah[3] = sXh[m0 + g + 8][sp + tq + 4]; al[3] = sXl[m0 + g + 8][sp + tq + 4];
#pragma unroll
            for (int j = 0; j < 8; j++) {
                const int kc = j * 8 + g;
                uint32_t bh0 = sAh[kc][sp + tq], bl0 = sAl[kc][sp + tq];
                uint32_t bh1 = sAh[kc][sp + tq + 4], bl1 = sAl[kc][sp + tq + 4];
                mma16(acc[j], ah, bh0, bh1);
                mma16(acc[j], ah, bl0, bl1);
                mma16(acc[j], al, bh0, bh1);
            }
        }
        __syncthreads();
    }

    // epilogue: rows d = d0+m0+g (half 0) and +8 (half 1); cols k = j*8+2tq(+1)
#pragma unroll
    for (int half = 0; half < 2; half++) {
        const int d = d0 + m0 + g + half * 8;
        float v[16];
        float s = 0.f;
#pragma unroll
        for (int j = 0; j < 8; j++) {
            const int k = j * 8 + 2 * tq;
            float c0 = cc[(size_t)k * DD + d];
            float c1 = cc[(size_t)(k + 1) * DD + d];
            float v0 = acc[j][half * 2 + 0] - 32.f * c0;
            float v1 = acc[j][half * 2 + 1] - 32.f * c1;
            v[j * 2] = v0; v[j * 2 + 1] = v1;
            s += v0 * v0 + v1 * v1;
        }
        s += __shfl_xor_sync(0xffffffffu, s, 1);
        s += __shfl_xor_sync(0xffffffffu, s, 2);
        float n1 = fmaxf(sqrtf(s), EPSN);
        float n2 = fmaxf(sqrtf(s) / n1, EPSN);
        float inv = 1.0f / (n1 * n2);
        float* dst = g_v + ((size_t)b * DD + d) * KK;
#pragma unroll
        for (int j = 0; j < 8; j++)
            *(float2*)(dst + j * 8 + 2 * tq) =
                make_float2(v[j * 2] * inv, v[j * 2 + 1] * inv);
    }
}

// ============================================================================
// Kernel 4: transpose g_v [b][dk] -> out [dk][b]
// ============================================================================
__global__ __launch_bounds__(256) void k_tr(float* __restrict__ out) {
    __shared__ float tile[32][33];
    const int bx = blockIdx.x * 32;   // dk
    const int by = blockIdx.y * 32;   // b
    const int tx = threadIdx.x & 31;
    const int ty = threadIdx.x >> 5;  // 0..7

#pragma unroll
    for (int i = 0; i < 32; i += 8)
        tile[ty + i][tx] = g_v[(size_t)(by + ty + i) * (DD * KK) + bx + tx];
    __syncthreads();
#pragma unroll
    for (int i = 0; i < 32; i += 8)
        out[(size_t)(bx + ty + i) * BB + by + tx] = tile[tx][ty + i];
}

// ============================================================================
extern "C" void kernel_launch(void* const* d_in, const int* in_sizes, int n_in,
                              void* d_out, int out_size) {
    const float* x  = (const float*)d_in[0];
    const float* wt = (const float*)d_in[1];
    const float* c  = (const float*)d_in[2];
    float* out = (float*)d_out;

    k_feat<<<dim3(NN / 256, BB), 256>>>(x, wt);

    k_softmax<<<BB * KK, 256>>>();

    k_vlad<<<dim3(DD / 128, BB), 256>>>(x, c);

    k_tr<<<dim3(DD * KK / 32, BB / 32), 256>>>(out);
}

// round 11
// speedup vs baseline: 2.5086x; 1.3456x over previous
#include <cuda_runtime.h>
#include <cstdint>

// NetVladCNN: B=64, D=512, H=W=32 (N=1024), K=64
// x: (B,D,H,W) fp32   w: (K,D)   c: (K,D)   out: (D,K,B) fp32
//
// Stage 1 (fp16 m16n8k16 mma, fp32 accum): features = w·x
// Stage 2 (fp32): softmax over h (sum_n a == 32 exactly)
// Stage 3 (fp16 mma): C[d,k] = sum_n x[d,n]*a[k,n]; V = C - 32*c^T (fp32);
//         warp-local k-normalize; g_v[b][d][k]
// Stage 4: transpose g_v [b][dk] -> out [dk][b]
//
// Error budget: V is dominated by the exact fp32 -32c term (|V|~32 vs einsum
// ~1.7), so fp16 operand rounding (~e-4 abs) lands at ~1e-5 relative.

#define BB 64
#define DD 512
#define NN 1024
#define KK 64
#define EPSN 1e-12f

__device__ float g_a[(size_t)BB * KK * NN];   // features / softmaxed a [b][k][n]
__device__ float g_v[(size_t)BB * DD * KK];   // normalized V [b][d][k]

// ---------- fp16 mma helpers ----------
__device__ __forceinline__ void mma16(float* c, const uint32_t* a, uint32_t b0,
                                      uint32_t b1) {
    asm volatile(
        "mma.sync.aligned.m16n8k16.row.col.f32.f16.f16.f32 "
        "{%0,%1,%2,%3}, {%4,%5,%6,%7}, {%8,%9}, {%0,%1,%2,%3};"
        : "+f"(c[0]), "+f"(c[1]), "+f"(c[2]), "+f"(c[3])
        : "r"(a[0]), "r"(a[1]), "r"(a[2]), "r"(a[3]), "r"(b0), "r"(b1));
}

// pack a contraction pair (e = even k, o = odd k) into one f16x2 reg (lo=even).
__device__ __forceinline__ uint32_t packh(float e, float o) {
    uint32_t r;
    asm("cvt.rn.f16x2.f32 %0, %1, %2;" : "=r"(r) : "f"(o), "f"(e));
    return r;
}

// ============================================================================
// Kernel 1: features GEMM (fp16 mma).
// Per b: M=64 (k), N'=256 (n tile), contraction d=512 in chunks of 32.
// 256 thr = 8 warps; warp tile = m32 x n64 (2 m-tiles x 8 n-frags).
// ============================================================================
#define WPAD 20
#define XPAD 264
__global__ __launch_bounds__(256, 2) void k_feat(const float* __restrict__ x,
                                                 const float* __restrict__ wt) {
    __shared__ uint32_t sW[64][WPAD];   // [k][d-pair 16] f16x2
    __shared__ uint32_t sX[16][XPAD];   // [d-pair][n 256] f16x2 (pair across d)

    const int b = blockIdx.y, n0 = blockIdx.x * 256;
    const int t = threadIdx.x, lane = t & 31, warp = t >> 5;
    const int g = lane >> 2, tq = lane & 3;
    const int k0 = (warp >> 2) * 32;     // warp m-base (k)
    const int nb = (warp & 3) * 64;      // warp n-base
    const float* xb = x + (size_t)b * DD * NN;

    float acc[2][8][4];
#pragma unroll
    for (int i = 0; i < 2; i++)
#pragma unroll
        for (int j = 0; j < 8; j++)
#pragma unroll
            for (int r = 0; r < 4; r++) acc[i][j][r] = 0.f;

    const int wrow = t & 63, wseg = t >> 6;   // w loader: 4 segs x 8 d
    const int xdp = t >> 4, xtx = t & 15;     // x loader: d-pair row, col group

    for (int d0 = 0; d0 < DD; d0 += 32) {
        // ---- w tile: 64k x 32d -> 16 d-pairs ----
        {
            const float* src = wt + (size_t)wrow * DD + d0 + wseg * 8;
            float4 v0 = *(const float4*)src;
            float4 v1 = *(const float4*)(src + 4);
            sW[wrow][wseg * 4 + 0] = packh(v0.x, v0.y);
            sW[wrow][wseg * 4 + 1] = packh(v0.z, v0.w);
            sW[wrow][wseg * 4 + 2] = packh(v1.x, v1.y);
            sW[wrow][wseg * 4 + 3] = packh(v1.z, v1.w);
        }
        // ---- x tile: 32d x 256n -> [16 dp][256 n], pairs across d-rows ----
        {
            const float* se = xb + (size_t)(d0 + 2 * xdp) * NN + n0;
            const float* so = se + NN;
#pragma unroll
            for (int q = 0; q < 4; q++) {
                const int col = xtx * 4 + 64 * q;
                float4 ve = *(const float4*)(se + col);
                float4 vo = *(const float4*)(so + col);
                *(uint4*)&sX[xdp][col] =
                    make_uint4(packh(ve.x, vo.x), packh(ve.y, vo.y),
                               packh(ve.z, vo.z), packh(ve.w, vo.w));
            }
        }
        __syncthreads();

#pragma unroll
        for (int s = 0; s < 2; s++) {
            const int sp = s * 8;
            uint32_t a[2][4];
#pragma unroll
            for (int mi = 0; mi < 2; mi++) {
                const int r0 = k0 + mi * 16 + g;
                a[mi][0] = sW[r0][sp + tq];
                a[mi][1] = sW[r0 + 8][sp + tq];
                a[mi][2] = sW[r0][sp + tq + 4];
                a[mi][3] = sW[r0 + 8][sp + tq + 4];
            }
#pragma unroll
            for (int j = 0; j < 8; j++) {
                const int n = nb + j * 8 + g;
                uint32_t b0 = sX[sp + tq][n];
                uint32_t b1 = sX[sp + tq + 4][n];
                mma16(acc[0][j], a[0], b0, b1);
                mma16(acc[1][j], a[1], b0, b1);
            }
        }
        __syncthreads();
    }

#pragma unroll
    for (int mi = 0; mi < 2; mi++) {
#pragma unroll
        for (int j = 0; j < 8; j++) {
            const int k = k0 + mi * 16 + g;
            const int n = n0 + nb + j * 8 + 2 * tq;
            *(float2*)&g_a[((size_t)b * KK + k) * NN + n] =
                make_float2(acc[mi][j][0], acc[mi][j][1]);
            *(float2*)&g_a[((size_t)b * KK + k + 8) * NN + n] =
                make_float2(acc[mi][j][2], acc[mi][j][3]);
        }
    }
}

// ============================================================================
// Kernel 2: softmax over h, per (b,k) row of 1024 = 32h x 32w.  (fp32)
// ============================================================================
__global__ __launch_bounds__(256) void k_softmax() {
    __shared__ float red[8][33];
    const size_t base = (size_t)blockIdx.x * NN;
    const int t = threadIdx.x;
    const int q = t >> 5, w = t & 31;

    float v[4];
#pragma unroll
    for (int u = 0; u < 4; u++) v[u] = g_a[base + t + 256 * u];

    float m = fmaxf(fmaxf(v[0], v[1]), fmaxf(v[2], v[3]));
    red[q][w] = m;
    __syncthreads();
    float mm = red[0][w];
#pragma unroll
    for (int qq = 1; qq < 8; qq++) mm = fmaxf(mm, red[qq][w]);
    __syncthreads();

    float s = 0.f;
#pragma unroll
    for (int u = 0; u < 4; u++) { v[u] = __expf(v[u] - mm); s += v[u]; }
    red[q][w] = s;
    __syncthreads();
    float ss = red[0][w];
#pragma unroll
    for (int qq = 1; qq < 8; qq++) ss += red[qq][w];

    float inv = 1.0f / ss;
#pragma unroll
    for (int u = 0; u < 4; u++) g_a[base + t + 256 * u] = v[u] * inv;
}

// ============================================================================
// Kernel 3: V GEMM (fp16 mma), output-flipped C[d,k].
// Per b: M=128 (d tile), N'=64 (all k), contraction n=1024 in chunks of 32.
// 256 thr = 8 warps; warp tile = m16(d) x n64(k) = 8 k-frags.
// Epilogue: V = C - 32*c^T; warp-local L2 norm over k; write g_v[b][d][k].
// ============================================================================
__global__ __launch_bounds__(256, 2) void k_vlad(const float* __restrict__ x,
                                                 const float* __restrict__ cc) {
    __shared__ uint32_t sA[64][WPAD];    // [k][n-pair 16] f16x2
    __shared__ uint32_t sX[128][WPAD];   // [d][n-pair 16] f16x2

    const int b = blockIdx.y, d0 = blockIdx.x * 128;
    const int t = threadIdx.x, lane = t & 31, warp = t >> 5;
    const int g = lane >> 2, tq = lane & 3;
    const int m0 = warp * 16;       // warp d-base within tile
    const float* xb = x + (size_t)b * DD * NN;
    const float* ab = g_a + (size_t)b * KK * NN;

    float acc[8][4];
#pragma unroll
    for (int j = 0; j < 8; j++)
#pragma unroll
        for (int r = 0; r < 4; r++) acc[j][r] = 0.f;

    const int arow = t & 63, aseg = t >> 6;   // a loader: 4 segs x 8 n
    const int xrow = t >> 1, xseg = t & 1;    // x loader: 2 segs x 16 n

    for (int n0 = 0; n0 < NN; n0 += 32) {
        {
            const float* src = ab + (size_t)arow * NN + n0 + aseg * 8;
            float4 v0 = *(const float4*)src;
            float4 v1 = *(const float4*)(src + 4);
            *(uint4*)&sA[arow][aseg * 4] =
                make_uint4(packh(v0.x, v0.y), packh(v0.z, v0.w),
                           packh(v1.x, v1.y), packh(v1.z, v1.w));
        }
        {
            const float* src = xb + (size_t)(d0 + xrow) * NN + n0 + xseg * 16;
#pragma unroll
            for (int q = 0; q < 2; q++) {
                float4 v0 = *(const float4*)(src + q * 8);
                float4 v1 = *(const float4*)(src + q * 8 + 4);
                *(uint4*)&sX[xrow][xseg * 8 + q * 4] =
                    make_uint4(packh(v0.x, v0.y), packh(v0.z, v0.w),
                               packh(v1.x, v1.y), packh(v1.z, v1.w));
            }
        }
        __syncthreads();

#pragma unroll
        for (int s = 0; s < 2; s++) {
            const int sp = s * 8;
            uint32_t a[4];
            a[0] = sX[m0 + g][sp + tq];
            a[1] = sX[m0 + g + 8][sp + tq];
            a[2] = sX[m0 + g][sp + tq + 4];
            a[3] = sX[m0 + g + 8][sp + tq + 4];
#pragma unroll
            for (int j = 0; j < 8; j++) {
                const int kc = j * 8 + g;
                uint32_t b0 = sA[kc][sp + tq];
                uint32_t b1 = sA[kc][sp + tq + 4];
                mma16(acc[j], a, b0, b1);
            }
        }
        __syncthreads();
    }

    // epilogue: rows d = d0+m0+g (half 0) and +8 (half 1); cols k = j*8+2tq(+1)
#pragma unroll
    for (int half = 0; half < 2; half++) {
        const int d = d0 + m0 + g + half * 8;
        float v[16];
        float s = 0.f;
#pragma unroll
        for (int j = 0; j < 8; j++) {
            const int k = j * 8 + 2 * tq;
            float c0 = cc[(size_t)k * DD + d];
            float c1 = cc[(size_t)(k + 1) * DD + d];
            float v0 = acc[j][half * 2 + 0] - 32.f * c0;
            float v1 = acc[j][half * 2 + 1] - 32.f * c1;
            v[j * 2] = v0; v[j * 2 + 1] = v1;
            s += v0 * v0 + v1 * v1;
        }
        s += __shfl_xor_sync(0xffffffffu, s, 1);
        s += __shfl_xor_sync(0xffffffffu, s, 2);
        float n1 = fmaxf(sqrtf(s), EPSN);
        float n2 = fmaxf(sqrtf(s) / n1, EPSN);
        float inv = 1.0f / (n1 * n2);
        float* dst = g_v + ((size_t)b * DD + d) * KK;
#pragma unroll
        for (int j = 0; j < 8; j++)
            *(float2*)(dst + j * 8 + 2 * tq) =
                make_float2(v[j * 2] * inv, v[j * 2 + 1] * inv);
    }
}

// ============================================================================
// Kernel 4: transpose g_v [b][dk] -> out [dk][b]
// ============================================================================
__global__ __launch_bounds__(256) void k_tr(float* __restrict__ out) {
    __shared__ float tile[32][33];
    const int bx = blockIdx.x * 32;   // dk
    const int by = blockIdx.y * 32;   // b
    const int tx = threadIdx.x & 31;
    const int ty = threadIdx.x >> 5;  // 0..7

#pragma unroll
    for (int i = 0; i < 32; i += 8)
        tile[ty + i][tx] = g_v[(size_t)(by + ty + i) * (DD * KK) + bx + tx];
    __syncthreads();
#pragma unroll
    for (int i = 0; i < 32; i += 8)
        out[(size_t)(bx + ty + i) * BB + by + tx] = tile[tx][ty + i];
}

// ============================================================================
extern "C" void kernel_launch(void* const* d_in, const int* in_sizes, int n_in,
                              void* d_out, int out_size) {
    const float* x  = (const float*)d_in[0];
    const float* wt = (const float*)d_in[1];
    const float* c  = (const float*)d_in[2];
    float* out = (float*)d_out;

    k_feat<<<dim3(NN / 256, BB), 256>>>(x, wt);

    k_softmax<<<BB * KK, 256>>>();

    k_vlad<<<dim3(DD / 128, BB), 256>>>(x, c);

    k_tr<<<dim3(DD * KK / 32, BB / 32), 256>>>(out);
}